// round 1
// baseline (speedup 1.0000x reference)
#include <cuda_runtime.h>
#include <math.h>
#include <stdint.h>

// VQ-VAE forward: enc(2x GEMM+ReLU) -> VQ (fused dist+argmin+gather) -> dec(2x GEMM)
// Shapes: N=16384, IN_DIM=1024, ENC_DIM=256, K=8192
#define NT   16384
#define DIN  1024
#define DE   256
#define KC   8192

// Scratch (static __device__ arrays: allocation-free per harness rules)
static __device__ float g_h  [(size_t)NT * DE];   // 16 MB
static __device__ float g_enc[(size_t)NT * DE];   // 16 MB
static __device__ float g_g  [(size_t)NT * DE];   // 16 MB
static __device__ float g_x2 [NT];
static __device__ float g_c2 [KC];

// ---------------------------------------------------------------------------
// Tiled fp32 SGEMM: C[M,Nn] = (opt ReLU)(A[M,Kk] @ B[Kk,Nn] + bias[Nn])
// BM=BN=128, BK=16, 256 threads, 8x8 per thread.
// Requires M%128==0, Nn%128==0, Kk%16==0 (all shapes here satisfy this).
// ---------------------------------------------------------------------------
template<bool RELU>
__global__ __launch_bounds__(256)
void sgemm_bias(const float* __restrict__ A, const float* __restrict__ B,
                const float* __restrict__ bias, float* __restrict__ C,
                int M, int Nn, int Kk)
{
    const int BM = 128, BN = 128, BK = 16;
    __shared__ float As[BK][BM];
    __shared__ float Bs[BK][BN];

    const int tid = threadIdx.x;
    const int tm  = tid >> 4;    // 0..15 (row group)
    const int tn  = tid & 15;    // 0..15 (col group)
    const int bm  = blockIdx.y * BM;
    const int bn  = blockIdx.x * BN;

    float acc[8][8];
#pragma unroll
    for (int i = 0; i < 8; i++)
#pragma unroll
        for (int j = 0; j < 8; j++) acc[i][j] = 0.f;

    for (int k0 = 0; k0 < Kk; k0 += BK) {
        // A tile: 128 rows x 16 k, stored transposed As[k][m]
#pragma unroll
        for (int i = 0; i < 2; i++) {
            int lin = tid + i * 256;          // float4 index, 0..511
            int row = lin >> 2;               // 4 float4 per row
            int kq  = lin & 3;
            float4 v = *(const float4*)(A + (size_t)(bm + row) * Kk + k0 + kq * 4);
            As[kq * 4 + 0][row] = v.x;
            As[kq * 4 + 1][row] = v.y;
            As[kq * 4 + 2][row] = v.z;
            As[kq * 4 + 3][row] = v.w;
        }
        // B tile: 16 k-rows x 128 n, row-major -> Bs[k][n]
#pragma unroll
        for (int i = 0; i < 2; i++) {
            int lin = tid + i * 256;
            int kr  = lin >> 5;               // 32 float4 per k-row
            int nq  = lin & 31;
            *(float4*)&Bs[kr][nq * 4] =
                *(const float4*)(B + (size_t)(k0 + kr) * Nn + bn + nq * 4);
        }
        __syncthreads();

#pragma unroll
        for (int k = 0; k < BK; k++) {
            float ra[8], rb[8];
#pragma unroll
            for (int i = 0; i < 8; i++) ra[i] = As[k][tm * 8 + i];
#pragma unroll
            for (int j = 0; j < 8; j++) rb[j] = Bs[k][tn * 8 + j];
#pragma unroll
            for (int i = 0; i < 8; i++)
#pragma unroll
                for (int j = 0; j < 8; j++) acc[i][j] += ra[i] * rb[j];
        }
        __syncthreads();
    }

#pragma unroll
    for (int i = 0; i < 8; i++) {
        int row = bm + tm * 8 + i;
#pragma unroll
        for (int j = 0; j < 8; j += 4) {
            int col = bn + tn * 8 + j;
            float4 v;
            v.x = acc[i][j + 0] + bias[col + 0];
            v.y = acc[i][j + 1] + bias[col + 1];
            v.z = acc[i][j + 2] + bias[col + 2];
            v.w = acc[i][j + 3] + bias[col + 3];
            if (RELU) {
                v.x = fmaxf(v.x, 0.f); v.y = fmaxf(v.y, 0.f);
                v.z = fmaxf(v.z, 0.f); v.w = fmaxf(v.w, 0.f);
            }
            *(float4*)(C + (size_t)row * Nn + col) = v;
        }
    }
}

// ---------------------------------------------------------------------------
// Row squared norms: out[row] = sum(X[row,:]^2). blockDim=(32,8), 1 warp/row.
// ncols must be a multiple of 128.
// ---------------------------------------------------------------------------
__global__ void row_sqnorm(const float* __restrict__ X, float* __restrict__ out,
                           int ncols)
{
    int row = blockIdx.x * 8 + threadIdx.y;
    float s = 0.f;
    for (int c = threadIdx.x * 4; c < ncols; c += 128) {
        float4 v = *(const float4*)(X + (size_t)row * ncols + c);
        s += v.x * v.x + v.y * v.y + v.z * v.z + v.w * v.w;
    }
#pragma unroll
    for (int o = 16; o > 0; o >>= 1) s += __shfl_xor_sync(0xFFFFFFFFu, s, o);
    if (threadIdx.x == 0) out[row] = s;
}

// ---------------------------------------------------------------------------
// Fused VQ: for 128 encoded rows, stream over all 8192 codewords computing
// m = c2[j] - 2*dot(enc_row, cw_j)  (x2 is a per-row constant -> argmin safe),
// track running (min, first-idx), then final dist = sqrt(max(x2 + m, 0)),
// and gather quantized rows. Never materializes the [N,K] matrix.
// ---------------------------------------------------------------------------
__global__ __launch_bounds__(256)
void vq_kernel(const float* __restrict__ enc, const float* __restrict__ cw,
               const float* __restrict__ c2,  const float* __restrict__ x2,
               float* __restrict__ out_idx, float* __restrict__ out_dist,
               float* __restrict__ out_quant)
{
    const int BM = 128, BN = 128, BK = 16;
    __shared__ float As[BK][BM];
    __shared__ float Bs[BK][BN];
    __shared__ float smin[128][16];
    __shared__ int   sidx[128][16];
    __shared__ int   widx[128];

    const int tid = threadIdx.x;
    const int tm  = tid >> 4;
    const int tn  = tid & 15;
    const int bm  = blockIdx.x * BM;

    float rmin[8];
    int   ridx[8];
#pragma unroll
    for (int i = 0; i < 8; i++) { rmin[i] = 3.4e38f; ridx[i] = 0; }

    for (int c0 = 0; c0 < KC; c0 += BN) {
        float acc[8][8];
#pragma unroll
        for (int i = 0; i < 8; i++)
#pragma unroll
            for (int j = 0; j < 8; j++) acc[i][j] = 0.f;

        for (int k0 = 0; k0 < DE; k0 += BK) {
            // encoded tile (rows bm..bm+127), transposed into As[k][m]
#pragma unroll
            for (int i = 0; i < 2; i++) {
                int lin = tid + i * 256;
                int row = lin >> 2;
                int kq  = lin & 3;
                float4 v = *(const float4*)(enc + (size_t)(bm + row) * DE + k0 + kq * 4);
                As[kq * 4 + 0][row] = v.x;
                As[kq * 4 + 1][row] = v.y;
                As[kq * 4 + 2][row] = v.z;
                As[kq * 4 + 3][row] = v.w;
            }
            // codeword tile (rows c0..c0+127) — NT layout, transposed into Bs[k][j]
#pragma unroll
            for (int i = 0; i < 2; i++) {
                int lin = tid + i * 256;
                int j   = lin >> 2;
                int kq  = lin & 3;
                float4 v = *(const float4*)(cw + (size_t)(c0 + j) * DE + k0 + kq * 4);
                Bs[kq * 4 + 0][j] = v.x;
                Bs[kq * 4 + 1][j] = v.y;
                Bs[kq * 4 + 2][j] = v.z;
                Bs[kq * 4 + 3][j] = v.w;
            }
            __syncthreads();

#pragma unroll
            for (int k = 0; k < BK; k++) {
                float ra[8], rb[8];
#pragma unroll
                for (int i = 0; i < 8; i++) ra[i] = As[k][tm * 8 + i];
#pragma unroll
                for (int j = 0; j < 8; j++) rb[j] = Bs[k][tn * 8 + j];
#pragma unroll
                for (int i = 0; i < 8; i++)
#pragma unroll
                    for (int j = 0; j < 8; j++) acc[i][j] += ra[i] * rb[j];
            }
            __syncthreads();
        }

        float cc[8];
#pragma unroll
        for (int j = 0; j < 8; j++) cc[j] = c2[c0 + tn * 8 + j];
#pragma unroll
        for (int i = 0; i < 8; i++) {
#pragma unroll
            for (int j = 0; j < 8; j++) {
                float d = cc[j] - 2.f * acc[i][j];
                int col = c0 + tn * 8 + j;   // ascending within thread & across chunks
                if (d < rmin[i]) { rmin[i] = d; ridx[i] = col; }
            }
        }
    }

    // reduce across the 16 column-group threads per row (preserve first-min)
#pragma unroll
    for (int i = 0; i < 8; i++) {
        smin[tm * 8 + i][tn] = rmin[i];
        sidx[tm * 8 + i][tn] = ridx[i];
    }
    __syncthreads();

    if (tid < 128) {
        float m = smin[tid][0];
        int   id = sidx[tid][0];
#pragma unroll
        for (int t = 1; t < 16; t++) {
            float v = smin[tid][t];
            int   w = sidx[tid][t];
            if (v < m || (v == m && w < id)) { m = v; id = w; }
        }
        float d2 = x2[bm + tid] + m;
        out_dist[bm + tid] = sqrtf(fmaxf(d2, 0.f));
        out_idx [bm + tid] = (float)id;
        widx[tid] = id;
    }
    __syncthreads();

    // gather quantized = codewords[idx] for these 128 rows (float4 coalesced)
    for (int t = tid; t < 128 * (DE / 4); t += 256) {
        int r = t / (DE / 4);
        int q = t % (DE / 4);
        *(float4*)(out_quant + (size_t)(bm + r) * DE + q * 4) =
            *(const float4*)(cw + (size_t)widx[r] * DE + q * 4);
    }
}

// ---------------------------------------------------------------------------
extern "C" void kernel_launch(void* const* d_in, const int* in_sizes, int n_in,
                              void* d_out, int out_size)
{
    (void)in_sizes; (void)n_in; (void)out_size;
    const float* x   = (const float*)d_in[0];
    const float* ew1 = (const float*)d_in[1];
    const float* eb1 = (const float*)d_in[2];
    const float* ew2 = (const float*)d_in[3];
    const float* eb2 = (const float*)d_in[4];
    const float* cw  = (const float*)d_in[5];
    const float* dw1 = (const float*)d_in[6];
    const float* db1 = (const float*)d_in[7];
    const float* dw2 = (const float*)d_in[8];
    const float* db2 = (const float*)d_in[9];

    float* out     = (float*)d_out;
    float* o_idx   = out;                                   // [N]   indices (as f32)
    float* o_dist  = out + NT;                              // [N]   distances
    float* o_rec   = out + 2 * NT;                          // [N, DIN] reconstructed
    float* o_quant = out + 2 * NT + (size_t)NT * DIN;       // [N, DE]  quantized

    float *h, *enc, *gg, *x2, *c2;
    cudaGetSymbolAddress((void**)&h,   g_h);
    cudaGetSymbolAddress((void**)&enc, g_enc);
    cudaGetSymbolAddress((void**)&gg,  g_g);
    cudaGetSymbolAddress((void**)&x2,  g_x2);
    cudaGetSymbolAddress((void**)&c2,  g_c2);

    dim3 blk(256);

    // Encoder
    sgemm_bias<true ><<<dim3(DE  / 128, NT / 128), blk>>>(x,   ew1, eb1, h,   NT, DE,  DIN);
    sgemm_bias<true ><<<dim3(DE  / 128, NT / 128), blk>>>(h,   ew2, eb2, enc, NT, DE,  DE);

    // Norms (c2 independent of encoder; x2 needs enc)
    row_sqnorm<<<KC / 8, dim3(32, 8)>>>(cw,  c2, DE);
    row_sqnorm<<<NT / 8, dim3(32, 8)>>>(enc, x2, DE);

    // Fused VQ distance + argmin + distance + gather
    vq_kernel<<<NT / 128, blk>>>(enc, cw, c2, x2, o_idx, o_dist, o_quant);

    // Decoder
    sgemm_bias<true ><<<dim3(DE  / 128, NT / 128), blk>>>(o_quant, dw1, db1, gg,    NT, DE,  DE);
    sgemm_bias<false><<<dim3(DIN / 128, NT / 128), blk>>>(gg,      dw2, db2, o_rec, NT, DIN, DE);
}

// round 2
// speedup vs baseline: 1.0046x; 1.0046x over previous
#include <cuda_runtime.h>
#include <math.h>
#include <stdint.h>

// VQ-VAE forward: enc(2x GEMM+ReLU) -> VQ (fused dist+argmin+gather) -> dec(2x GEMM)
// Shapes: N=16384, IN_DIM=1024, ENC_DIM=256, K=8192
#define NT   16384
#define DIN  1024
#define DE   256
#define KC   8192

// Scratch (static __device__ arrays: allocation-free per harness rules)
static __device__ float g_h  [(size_t)NT * DE];   // 16 MB
static __device__ float g_enc[(size_t)NT * DE];   // 16 MB
static __device__ float g_g  [(size_t)NT * DE];   // 16 MB
static __device__ float g_x2 [NT];
static __device__ float g_c2 [KC];

// ---------------------------------------------------------------------------
// Tiled fp32 SGEMM: C[M,Nn] = (opt ReLU)(A[M,Kk] @ B[Kk,Nn] + bias[Nn])
// BM=BN=128, BK=16, 256 threads, 8x8 per thread.
// Requires M%128==0, Nn%128==0, Kk%16==0 (all shapes here satisfy this).
// ---------------------------------------------------------------------------
template<bool RELU>
__global__ __launch_bounds__(256)
void sgemm_bias(const float* __restrict__ A, const float* __restrict__ B,
                const float* __restrict__ bias, float* __restrict__ C,
                int M, int Nn, int Kk)
{
    const int BM = 128, BN = 128, BK = 16;
    __shared__ float As[BK][BM];
    __shared__ float Bs[BK][BN];

    const int tid = threadIdx.x;
    const int tm  = tid >> 4;    // 0..15 (row group)
    const int tn  = tid & 15;    // 0..15 (col group)
    const int bm  = blockIdx.y * BM;
    const int bn  = blockIdx.x * BN;

    float acc[8][8];
#pragma unroll
    for (int i = 0; i < 8; i++)
#pragma unroll
        for (int j = 0; j < 8; j++) acc[i][j] = 0.f;

    for (int k0 = 0; k0 < Kk; k0 += BK) {
        // A tile: 128 rows x 16 k, stored transposed As[k][m]
#pragma unroll
        for (int i = 0; i < 2; i++) {
            int lin = tid + i * 256;          // float4 index, 0..511
            int row = lin >> 2;               // 4 float4 per row
            int kq  = lin & 3;
            float4 v = *(const float4*)(A + (size_t)(bm + row) * Kk + k0 + kq * 4);
            As[kq * 4 + 0][row] = v.x;
            As[kq * 4 + 1][row] = v.y;
            As[kq * 4 + 2][row] = v.z;
            As[kq * 4 + 3][row] = v.w;
        }
        // B tile: 16 k-rows x 128 n, row-major -> Bs[k][n]
#pragma unroll
        for (int i = 0; i < 2; i++) {
            int lin = tid + i * 256;
            int kr  = lin >> 5;               // 32 float4 per k-row
            int nq  = lin & 31;
            *(float4*)&Bs[kr][nq * 4] =
                *(const float4*)(B + (size_t)(k0 + kr) * Nn + bn + nq * 4);
        }
        __syncthreads();

#pragma unroll
        for (int k = 0; k < BK; k++) {
            float ra[8], rb[8];
#pragma unroll
            for (int i = 0; i < 8; i++) ra[i] = As[k][tm * 8 + i];
#pragma unroll
            for (int j = 0; j < 8; j++) rb[j] = Bs[k][tn * 8 + j];
#pragma unroll
            for (int i = 0; i < 8; i++)
#pragma unroll
                for (int j = 0; j < 8; j++) acc[i][j] += ra[i] * rb[j];
        }
        __syncthreads();
    }

#pragma unroll
    for (int i = 0; i < 8; i++) {
        int row = bm + tm * 8 + i;
#pragma unroll
        for (int j = 0; j < 8; j += 4) {
            int col = bn + tn * 8 + j;
            float4 v;
            v.x = acc[i][j + 0] + bias[col + 0];
            v.y = acc[i][j + 1] + bias[col + 1];
            v.z = acc[i][j + 2] + bias[col + 2];
            v.w = acc[i][j + 3] + bias[col + 3];
            if (RELU) {
                v.x = fmaxf(v.x, 0.f); v.y = fmaxf(v.y, 0.f);
                v.z = fmaxf(v.z, 0.f); v.w = fmaxf(v.w, 0.f);
            }
            *(float4*)(C + (size_t)row * Nn + col) = v;
        }
    }
}

// ---------------------------------------------------------------------------
// Row squared norms: out[row] = sum(X[row,:]^2). blockDim=(32,8), 1 warp/row.
// ncols must be a multiple of 128.
// ---------------------------------------------------------------------------
__global__ void row_sqnorm(const float* __restrict__ X, float* __restrict__ out,
                           int ncols)
{
    int row = blockIdx.x * 8 + threadIdx.y;
    float s = 0.f;
    for (int c = threadIdx.x * 4; c < ncols; c += 128) {
        float4 v = *(const float4*)(X + (size_t)row * ncols + c);
        s += v.x * v.x + v.y * v.y + v.z * v.z + v.w * v.w;
    }
#pragma unroll
    for (int o = 16; o > 0; o >>= 1) s += __shfl_xor_sync(0xFFFFFFFFu, s, o);
    if (threadIdx.x == 0) out[row] = s;
}

// ---------------------------------------------------------------------------
// Fused VQ: for 128 encoded rows, stream over all 8192 codewords computing
// m = c2[j] - 2*dot(enc_row, cw_j)  (x2 is a per-row constant -> argmin safe),
// track running (min, first-idx), then final dist = sqrt(max(x2 + m, 0)),
// and gather quantized rows. Never materializes the [N,K] matrix.
// ---------------------------------------------------------------------------
__global__ __launch_bounds__(256)
void vq_kernel(const float* __restrict__ enc, const float* __restrict__ cw,
               const float* __restrict__ c2,  const float* __restrict__ x2,
               float* __restrict__ out_idx, float* __restrict__ out_dist,
               float* __restrict__ out_quant)
{
    const int BM = 128, BN = 128, BK = 16;
    __shared__ float As[BK][BM];
    __shared__ float Bs[BK][BN];
    __shared__ float smin[128][16];
    __shared__ int   sidx[128][16];
    __shared__ int   widx[128];

    const int tid = threadIdx.x;
    const int tm  = tid >> 4;
    const int tn  = tid & 15;
    const int bm  = blockIdx.x * BM;

    float rmin[8];
    int   ridx[8];
#pragma unroll
    for (int i = 0; i < 8; i++) { rmin[i] = 3.4e38f; ridx[i] = 0; }

    for (int c0 = 0; c0 < KC; c0 += BN) {
        float acc[8][8];
#pragma unroll
        for (int i = 0; i < 8; i++)
#pragma unroll
            for (int j = 0; j < 8; j++) acc[i][j] = 0.f;

        for (int k0 = 0; k0 < DE; k0 += BK) {
            // encoded tile (rows bm..bm+127), transposed into As[k][m]
#pragma unroll
            for (int i = 0; i < 2; i++) {
                int lin = tid + i * 256;
                int row = lin >> 2;
                int kq  = lin & 3;
                float4 v = *(const float4*)(enc + (size_t)(bm + row) * DE + k0 + kq * 4);
                As[kq * 4 + 0][row] = v.x;
                As[kq * 4 + 1][row] = v.y;
                As[kq * 4 + 2][row] = v.z;
                As[kq * 4 + 3][row] = v.w;
            }
            // codeword tile (rows c0..c0+127) — NT layout, transposed into Bs[k][j]
#pragma unroll
            for (int i = 0; i < 2; i++) {
                int lin = tid + i * 256;
                int j   = lin >> 2;
                int kq  = lin & 3;
                float4 v = *(const float4*)(cw + (size_t)(c0 + j) * DE + k0 + kq * 4);
                Bs[kq * 4 + 0][j] = v.x;
                Bs[kq * 4 + 1][j] = v.y;
                Bs[kq * 4 + 2][j] = v.z;
                Bs[kq * 4 + 3][j] = v.w;
            }
            __syncthreads();

#pragma unroll
            for (int k = 0; k < BK; k++) {
                float ra[8], rb[8];
#pragma unroll
                for (int i = 0; i < 8; i++) ra[i] = As[k][tm * 8 + i];
#pragma unroll
                for (int j = 0; j < 8; j++) rb[j] = Bs[k][tn * 8 + j];
#pragma unroll
                for (int i = 0; i < 8; i++)
#pragma unroll
                    for (int j = 0; j < 8; j++) acc[i][j] += ra[i] * rb[j];
            }
            __syncthreads();
        }

        float cc[8];
#pragma unroll
        for (int j = 0; j < 8; j++) cc[j] = c2[c0 + tn * 8 + j];
#pragma unroll
        for (int i = 0; i < 8; i++) {
#pragma unroll
            for (int j = 0; j < 8; j++) {
                float d = cc[j] - 2.f * acc[i][j];
                int col = c0 + tn * 8 + j;   // ascending within thread & across chunks
                if (d < rmin[i]) { rmin[i] = d; ridx[i] = col; }
            }
        }
    }

    // reduce across the 16 column-group threads per row (preserve first-min)
#pragma unroll
    for (int i = 0; i < 8; i++) {
        smin[tm * 8 + i][tn] = rmin[i];
        sidx[tm * 8 + i][tn] = ridx[i];
    }
    __syncthreads();

    if (tid < 128) {
        float m = smin[tid][0];
        int   id = sidx[tid][0];
#pragma unroll
        for (int t = 1; t < 16; t++) {
            float v = smin[tid][t];
            int   w = sidx[tid][t];
            if (v < m || (v == m && w < id)) { m = v; id = w; }
        }
        float d2 = x2[bm + tid] + m;
        out_dist[bm + tid] = sqrtf(fmaxf(d2, 0.f));
        out_idx [bm + tid] = (float)id;
        widx[tid] = id;
    }
    __syncthreads();

    // gather quantized = codewords[idx] for these 128 rows (float4 coalesced)
    for (int t = tid; t < 128 * (DE / 4); t += 256) {
        int r = t / (DE / 4);
        int q = t % (DE / 4);
        *(float4*)(out_quant + (size_t)(bm + r) * DE + q * 4) =
            *(const float4*)(cw + (size_t)widx[r] * DE + q * 4);
    }
}

// ---------------------------------------------------------------------------
extern "C" void kernel_launch(void* const* d_in, const int* in_sizes, int n_in,
                              void* d_out, int out_size)
{
    (void)in_sizes; (void)n_in; (void)out_size;
    const float* x   = (const float*)d_in[0];
    const float* ew1 = (const float*)d_in[1];
    const float* eb1 = (const float*)d_in[2];
    const float* ew2 = (const float*)d_in[3];
    const float* eb2 = (const float*)d_in[4];
    const float* cw  = (const float*)d_in[5];
    const float* dw1 = (const float*)d_in[6];
    const float* db1 = (const float*)d_in[7];
    const float* dw2 = (const float*)d_in[8];
    const float* db2 = (const float*)d_in[9];

    float* out     = (float*)d_out;
    float* o_idx   = out;                                   // [N]   indices (as f32)
    float* o_dist  = out + NT;                              // [N]   distances
    float* o_rec   = out + 2 * NT;                          // [N, DIN] reconstructed
    float* o_quant = out + 2 * NT + (size_t)NT * DIN;       // [N, DE]  quantized

    float *h, *enc, *gg, *x2, *c2;
    cudaGetSymbolAddress((void**)&h,   g_h);
    cudaGetSymbolAddress((void**)&enc, g_enc);
    cudaGetSymbolAddress((void**)&gg,  g_g);
    cudaGetSymbolAddress((void**)&x2,  g_x2);
    cudaGetSymbolAddress((void**)&c2,  g_c2);

    dim3 blk(256);

    // Encoder
    sgemm_bias<true ><<<dim3(DE  / 128, NT / 128), blk>>>(x,   ew1, eb1, h,   NT, DE,  DIN);
    sgemm_bias<true ><<<dim3(DE  / 128, NT / 128), blk>>>(h,   ew2, eb2, enc, NT, DE,  DE);

    // Norms (c2 independent of encoder; x2 needs enc)
    row_sqnorm<<<KC / 8, dim3(32, 8)>>>(cw,  c2, DE);
    row_sqnorm<<<NT / 8, dim3(32, 8)>>>(enc, x2, DE);

    // Fused VQ distance + argmin + distance + gather
    vq_kernel<<<NT / 128, blk>>>(enc, cw, c2, x2, o_idx, o_dist, o_quant);

    // Decoder
    sgemm_bias<true ><<<dim3(DE  / 128, NT / 128), blk>>>(o_quant, dw1, db1, gg,    NT, DE,  DE);
    sgemm_bias<false><<<dim3(DIN / 128, NT / 128), blk>>>(gg,      dw2, db2, o_rec, NT, DIN, DE);
}